// round 14
// baseline (speedup 1.0000x reference)
#include <cuda_runtime.h>
#include <cuda_fp16.h>
#include <math_constants.h>
#include <cstdint>

#define BB   2
#define TT   2048
#define KD   1024
#define NH   16
#define HD   64
#define MTOT (BB*TT)

// ---------------- scratch (__device__ globals, allocation-free) -------------
__device__ __half g_xh [(size_t)MTOT * KD];
__device__ __half g_wqh[(size_t)KD   * KD];
__device__ __half g_wkh[(size_t)KD   * KD];
__device__ __half g_wvh[(size_t)KD   * KD];
__device__ __half g_wuh[(size_t)KD   * KD];
__device__ __half g_qh [(size_t)MTOT * KD];
__device__ __half g_kh [(size_t)MTOT * KD];
__device__ __half g_vh [(size_t)MTOT * KD];
__device__ __half g_oh [(size_t)MTOT * KD];

// ---------------- helpers ----------------------------------------------------
__device__ __forceinline__ uint32_t smem_u32(const void* p) {
    uint32_t a;
    asm("{ .reg .u64 t; cvta.to.shared.u64 t, %1; cvt.u32.u64 %0, t; }"
        : "=r"(a) : "l"(p));
    return a;
}
__device__ __forceinline__ void cp16(uint32_t dst, const void* src) {
    asm volatile("cp.async.cg.shared.global [%0], [%1], 16;" :: "r"(dst), "l"(src));
}
__device__ __forceinline__ void cp_commit() {
    asm volatile("cp.async.commit_group;" ::: "memory");
}
template <int N>
__device__ __forceinline__ void cp_wait() {
    asm volatile("cp.async.wait_group %0;" :: "n"(N) : "memory");
}
__device__ __forceinline__ void ldm_x4(uint32_t* r, uint32_t addr) {
    asm volatile("ldmatrix.sync.aligned.m8n8.x4.shared.b16 {%0,%1,%2,%3}, [%4];"
                 : "=r"(r[0]), "=r"(r[1]), "=r"(r[2]), "=r"(r[3]) : "r"(addr));
}
__device__ __forceinline__ void ldm_x4_t(uint32_t* r, uint32_t addr) {
    asm volatile("ldmatrix.sync.aligned.m8n8.x4.trans.shared.b16 {%0,%1,%2,%3}, [%4];"
                 : "=r"(r[0]), "=r"(r[1]), "=r"(r[2]), "=r"(r[3]) : "r"(addr));
}
__device__ __forceinline__ void mma_f16(float* c, const uint32_t* a, const uint32_t* b) {
    asm volatile(
        "mma.sync.aligned.m16n8k16.row.col.f32.f16.f16.f32 "
        "{%0,%1,%2,%3}, {%4,%5,%6,%7}, {%8,%9}, {%0,%1,%2,%3};"
        : "+f"(c[0]), "+f"(c[1]), "+f"(c[2]), "+f"(c[3])
        : "r"(a[0]), "r"(a[1]), "r"(a[2]), "r"(a[3]), "r"(b[0]), "r"(b[1]));
}
// fp16-accumulator MMA (C/D fragments are 2 regs of packed half2)
__device__ __forceinline__ void mma_f16acc(uint32_t* c, const uint32_t* a, const uint32_t* b) {
    asm volatile(
        "mma.sync.aligned.m16n8k16.row.col.f16.f16.f16.f16 "
        "{%0,%1}, {%2,%3,%4,%5}, {%6,%7}, {%0,%1};"
        : "+r"(c[0]), "+r"(c[1])
        : "r"(a[0]), "r"(a[1]), "r"(a[2]), "r"(a[3]), "r"(b[0]), "r"(b[1]));
}
__device__ __forceinline__ uint32_t pack_h2(float a, float b) {
    __half2 h = __floats2half2_rn(a, b);
    return *(uint32_t*)&h;
}
__device__ __forceinline__ uint32_t sw128(uint32_t off) {
    return off ^ ((off >> 3) & 0x70);
}

// ---------------- fused fp32 -> fp16 conversion ------------------------------
__global__ void cvt_kernel(const float* __restrict__ x,  const float* __restrict__ wq,
                           const float* __restrict__ wk, const float* __restrict__ wv,
                           const float* __restrict__ wu)
{
    const int which = blockIdx.y;
    const float* in;
    __half* out;
    int rows;
    switch (which) {
        case 0: in = x;  out = g_xh;  rows = MTOT; break;
        case 1: in = wq; out = g_wqh; rows = KD;   break;
        case 2: in = wk; out = g_wkh; rows = KD;   break;
        case 3: in = wv; out = g_wvh; rows = KD;   break;
        default: in = wu; out = g_wuh; rows = KD;  break;
    }
    int r = blockIdx.x;
    if (r >= rows) return;
    int c = threadIdx.x * 4;
    float4 a = *(const float4*)(in + (size_t)r * KD + c);
    uint2 o;
    o.x = pack_h2(a.x, a.y);
    o.y = pack_h2(a.z, a.w);
    *(uint2*)(out + (size_t)r * KD + c) = o;
}

// ---------------- mma.sync fp16 GEMM: 128x128 tile, BK=64, 3-stage (R8) ------
#define GROW   144                       // bytes per smem row (64 fp16 + 8 pad)
#define TILE_B (128 * GROW)              // 18432 per matrix tile
#define STAGE_ALL (2 * TILE_B)           // 36864 per stage (A+B)
#define SMEM_MMA (3 * STAGE_ALL)         // 110592

__device__ __forceinline__ void load_stage(
    const __half* __restrict__ Ag, const __half* __restrict__ Wg,
    uint32_t sA, uint32_t sB, int tid)
{
#pragma unroll
    for (int i = 0; i < 4; i++) {
        int c = tid + i * 256;           // 0..1023
        int r = c >> 3;                  // 0..127
        int q = c & 7;                   // 16B chunk
        cp16(sA + r * GROW + q * 16, Ag + (size_t)r * KD + q * 8);
        cp16(sB + r * GROW + q * 16, Wg + (size_t)r * KD + q * 8);
    }
}

__device__ __forceinline__ void tgemm_mma(
    const __half* __restrict__ A2, const __half* __restrict__ W2,
    float scale, int mode,
    float* __restrict__ Cf, const float* __restrict__ bias,
    __half* __restrict__ Ch)
{
    extern __shared__ char sm[];
    const uint32_t smb = smem_u32(sm);
    const int tid    = threadIdx.x;
    const int lane   = tid & 31;
    const int wid    = tid >> 5;
    const int warp_m = wid & 1;
    const int warp_n = wid >> 1;
    const int m0     = blockIdx.y * 128;
    const int n0     = blockIdx.x * 128;

    const __half* Abase = A2 + (size_t)m0 * KD;
    const __half* Wbase = W2 + (size_t)n0 * KD;

    float acc[4][4][4];
#pragma unroll
    for (int i = 0; i < 4; i++)
#pragma unroll
        for (int j = 0; j < 4; j++)
#pragma unroll
            for (int r = 0; r < 4; r++) acc[i][j][r] = 0.f;

    const int NIT = 16;                  // 1024 / 64

    load_stage(Abase,      Wbase,      smb,             smb + TILE_B,             tid);
    cp_commit();
    load_stage(Abase + 64, Wbase + 64, smb + STAGE_ALL, smb + STAGE_ALL + TILE_B, tid);
    cp_commit();

    const int a_row = (lane & 15);
    const int a_col = (lane >> 4) << 3;
    const int b_row = ((lane >> 4) << 3) + (lane & 7);
    const int b_col = ((lane >> 3) & 1) << 3;

    for (int it = 0; it < NIT; it++) {
        if (it == NIT - 1) cp_wait<0>(); else cp_wait<1>();
        __syncthreads();
        if (it + 2 < NIT) {
            uint32_t sl = smb + ((it + 2) % 3) * STAGE_ALL;
            load_stage(Abase + (it + 2) * 64, Wbase + (it + 2) * 64,
                       sl, sl + TILE_B, tid);
            cp_commit();
        }

        const uint32_t sA = smb + (it % 3) * STAGE_ALL;
        const uint32_t sB = sA + TILE_B;

#pragma unroll
        for (int ks = 0; ks < 4; ks++) {
            uint32_t a[4][4], b[2][4];
#pragma unroll
            for (int mi = 0; mi < 4; mi++)
                ldm_x4(a[mi], sA + (warp_m * 64 + mi * 16 + a_row) * GROW
                              + (ks * 16 + a_col) * 2);
#pragma unroll
            for (int ni = 0; ni < 2; ni++)
                ldm_x4(b[ni], sB + (warp_n * 32 + ni * 16 + b_row) * GROW
                              + (ks * 16 + b_col) * 2);
#pragma unroll
            for (int mi = 0; mi < 4; mi++)
#pragma unroll
                for (int nj = 0; nj < 4; nj++)
                    mma_f16(acc[mi][nj], a[mi], &b[nj >> 1][(nj & 1) * 2]);
        }
    }

#pragma unroll
    for (int mi = 0; mi < 4; mi++) {
#pragma unroll
        for (int nj = 0; nj < 4; nj++) {
            int row = m0 + warp_m * 64 + mi * 16 + (lane >> 2);
            int col = n0 + warp_n * 32 + nj * 8 + (lane & 3) * 2;
            float v00 = acc[mi][nj][0] * scale, v01 = acc[mi][nj][1] * scale;
            float v10 = acc[mi][nj][2] * scale, v11 = acc[mi][nj][3] * scale;
            if (mode == 0) {
                float b0 = bias[col], b1 = bias[col + 1];
                *(float2*)(Cf + (size_t)row * KD + col)       = make_float2(v00 + b0, v01 + b1);
                *(float2*)(Cf + (size_t)(row + 8) * KD + col) = make_float2(v10 + b0, v11 + b1);
            } else {
                *(uint32_t*)(Ch + (size_t)row * KD + col)       = pack_h2(v00, v01);
                *(uint32_t*)(Ch + (size_t)(row + 8) * KD + col) = pack_h2(v10, v11);
            }
        }
    }
}

// q/k scale: 1024^(-1/4) * sqrt(log2(e))  -> S lands directly in log2 domain
#define QK_SCALE 0.2123296923175822f

__global__ __launch_bounds__(256, 2) void qkv_mma() {
    if (blockIdx.z == 0)
        tgemm_mma(g_xh, g_wqh, QK_SCALE, 1, nullptr, nullptr, g_qh);
    else if (blockIdx.z == 1)
        tgemm_mma(g_xh, g_wkh, QK_SCALE, 1, nullptr, nullptr, g_kh);
    else
        tgemm_mma(g_xh, g_wvh, 1.0f, 1, nullptr, nullptr, g_vh);
}

__global__ __launch_bounds__(256, 2) void out_mma(const float* __restrict__ bu,
                                                  float* __restrict__ out) {
    tgemm_mma(g_oh, g_wuh, 1.0f, 0, out, bu, nullptr);
}

// ---------------- tensorized flash attention (fp16, R11 + S/PV pipelining) ---
// CTA: 64 q-rows x (head, batch). 4 warps, 16 rows each, Bc = 128, 3-stage,
// 2 CTAs/SM (R11-proven shape). Cross-tile software pipeline: S(jb+1) is
// computed between exp(jb) and PV(jb) with double-buffered f16 S accumulators,
// hiding the HMMA->exp dependency latency behind PV's tensor burst.
#define AKV_STAGE 32768                         // K 16K + V 16K
#define ATT_SMEM  (8192 + 3 * AKV_STAGE)        // 106496 -> 2 CTAs/SM

__device__ __forceinline__ void attn_load_kv(const __half* Kg, const __half* Vg,
                                             size_t base, uint32_t sK, int tid)
{
#pragma unroll
    for (int i = 0; i < 8; i++) {
        int c = tid + i * 128, r = c >> 3, q = c & 7;   // 128 rows x 8 chunks
        uint32_t so = sw128(r * 128 + q * 16);
        size_t   go = (base + r) * KD + q * 8;
        cp16(sK + so,         Kg + go);
        cp16(sK + 16384 + so, Vg + go);
    }
}

// S = Q * K^T for one 128-col tile, f16 accumulators (log2-domain logits)
__device__ __forceinline__ void attn_S(uint32_t sacc[16][2], uint32_t sK,
                                       const uint32_t qa[4][4], int lane)
{
#pragma unroll
    for (int j = 0; j < 16; j++) { sacc[j][0] = 0u; sacc[j][1] = 0u; }
#pragma unroll
    for (int ks = 0; ks < 4; ks++) {
#pragma unroll
        for (int jn = 0; jn < 8; jn++) {
            uint32_t kb[4];
            int br = jn * 16 + ((lane >> 4) << 3) + (lane & 7);
            int bc = ks * 16 + (((lane >> 3) & 1) << 3);
            ldm_x4(kb, sK + sw128(br * 128 + bc * 2));
            mma_f16acc(sacc[2 * jn],     qa[ks], kb);
            mma_f16acc(sacc[2 * jn + 1], qa[ks], kb + 2);
        }
    }
}

// P = exp2(S) in place on the f16 accumulator registers; l from rounded P
__device__ __forceinline__ void attn_exp(const uint32_t sacc[16][2],
                                         uint32_t ph[8][4], float& l0, float& l1)
{
    __half2 sA0 = __float2half2_rn(0.f), sA1 = sA0;
    __half2 sB0 = sA0, sB1 = sA0;
#pragma unroll
    for (int j = 0; j < 16; j++) {
        __half2 pA = h2exp2(*(__half2*)&sacc[j][0]);   // row lane/4
        __half2 pB = h2exp2(*(__half2*)&sacc[j][1]);   // row lane/4 + 8
        if (j & 1) { sA1 = __hadd2(sA1, pA); sB1 = __hadd2(sB1, pB); }
        else       { sA0 = __hadd2(sA0, pA); sB0 = __hadd2(sB0, pB); }
        int kv = j >> 1, o = (j & 1) * 2;
        ph[kv][o]     = *(uint32_t*)&pA;
        ph[kv][o + 1] = *(uint32_t*)&pB;
    }
    float2 fA0 = __half22float2(sA0), fA1 = __half22float2(sA1);
    float2 fB0 = __half22float2(sB0), fB1 = __half22float2(sB1);
    l0 += (fA0.x + fA0.y) + (fA1.x + fA1.y);
    l1 += (fB0.x + fB0.y) + (fB1.x + fB1.y);
}

// O += P * V (fp32 accumulators)
__device__ __forceinline__ void attn_PV(float oacc[8][4], const uint32_t ph[8][4],
                                        uint32_t sV, int lane)
{
#pragma unroll
    for (int kv = 0; kv < 8; kv++) {
#pragma unroll
        for (int nb = 0; nb < 4; nb++) {
            uint32_t vb[4];
            int vr = kv * 16 + (((lane >> 3) & 1) << 3) + (lane & 7);
            int vc = nb * 16 + ((lane >> 4) << 3);
            ldm_x4_t(vb, sV + sw128(vr * 128 + vc * 2));
            mma_f16(oacc[2 * nb],     ph[kv], vb);
            mma_f16(oacc[2 * nb + 1], ph[kv], vb + 2);
        }
    }
}

__global__ __launch_bounds__(128, 2) void attn_mma()
{
    extern __shared__ char sm[];
    const uint32_t smb = smem_u32(sm);
    const int tid = threadIdx.x, lane = tid & 31, w = tid >> 5;
    const int qb = blockIdx.x, h = blockIdx.y, b = blockIdx.z;

    const __half* Qg = g_qh + (size_t)(b * TT + qb * 64) * KD + h * HD;
    const __half* Kg = g_kh + (size_t)(b * TT) * KD + h * HD;
    const __half* Vg = g_vh + (size_t)(b * TT) * KD + h * HD;

    const uint32_t sQ = smb;
    const int NTILE = TT / 128;          // 16

    // group0: Q + KV(0);  group1: KV(1)
#pragma unroll
    for (int i = 0; i < 4; i++) {
        int c = tid + i * 128, r = c >> 3, q = c & 7;
        cp16(sQ + sw128(r * 128 + q * 16), Qg + (size_t)r * KD + q * 8);
    }
    attn_load_kv(Kg, Vg, 0, smb + 8192, tid);
    cp_commit();
    attn_load_kv(Kg, Vg, 128, smb + 8192 + AKV_STAGE, tid);
    cp_commit();

    float oacc[8][4];
#pragma unroll
    for (int f = 0; f < 8; f++)
#pragma unroll
        for (int r = 0; r < 4; r++) oacc[f][r] = 0.f;
    float l0 = 0.f, l1 = 0.f;

    // wait group0 (Q + KV0), load Q frags, compute S(0)
    cp_wait<1>();
    __syncthreads();
    uint32_t qa[4][4];
#pragma unroll
    for (int ks = 0; ks < 4; ks++) {
        int ar = w * 16 + (lane & 15);
        int ac = ks * 16 + ((lane >> 4) << 3);
        ldm_x4(qa[ks], sQ + sw128(ar * 128 + ac * 2));
    }

    uint32_t saccA[16][2], saccB[16][2];
    attn_S(saccA, smb + 8192, qa, lane);

    uint32_t ph[8][4];

#pragma unroll 1
    for (int jb = 0; jb < NTILE; jb += 2) {
        // ---- iteration jb (S in saccA) ----
        attn_exp(saccA, ph, l0, l1);
        __syncthreads();                         // PV(jb-1) readers done
        if (jb + 2 < NTILE) {
            attn_load_kv(Kg, Vg, (size_t)(jb + 2) * 128,
                         smb + 8192 + ((jb + 2) % 3) * AKV_STAGE, tid);
            cp_commit();
            cp_wait<1>();                        // KV(jb+1) landed
        } else {
            cp_wait<0>();
        }
        attn_S(saccB, smb + 8192 + ((jb + 1) % 3) * AKV_STAGE, qa, lane);
        attn_PV(oacc, ph, smb + 8192 + (jb % 3) * AKV_STAGE + 16384, lane);

        // ---- iteration jb+1 (S in saccB) ----
        attn_exp(saccB, ph, l0, l1);
        __syncthreads();                         // PV(jb) readers done
        if (jb + 3 < NTILE) {
            attn_load_kv(Kg, Vg, (size_t)(jb + 3) * 128,
                         smb + 8192 + ((jb + 3) % 3) * AKV_STAGE, tid);
            cp_commit();
            cp_wait<1>();                        // KV(jb+2) landed
        } else {
            cp_wait<0>();
        }
        if (jb + 2 < NTILE)
            attn_S(saccA, smb + 8192 + ((jb + 2) % 3) * AKV_STAGE, qa, lane);
        attn_PV(oacc, ph, smb + 8192 + ((jb + 1) % 3) * AKV_STAGE + 16384, lane);
    }

    l0 += __shfl_xor_sync(0xffffffffu, l0, 1);
    l0 += __shfl_xor_sync(0xffffffffu, l0, 2);
    l1 += __shfl_xor_sync(0xffffffffu, l1, 1);
    l1 += __shfl_xor_sync(0xffffffffu, l1, 2);
    float inv0 = 1.f / l0, inv1 = 1.f / l1;

    size_t r0g = (size_t)(b * TT + qb * 64 + w * 16 + (lane >> 2));
    size_t r1g = r0g + 8;
    int colb = h * HD + 2 * (lane & 3);
#pragma unroll
    for (int f = 0; f < 8; f++) {
        int col = colb + f * 8;
        *(uint32_t*)(g_oh + r0g * KD + col) = pack_h2(oacc[f][0] * inv0, oacc[f][1] * inv0);
        *(uint32_t*)(g_oh + r1g * KD + col) = pack_h2(oacc[f][2] * inv1, oacc[f][3] * inv1);
    }
}

// ---------------------------------------------------------------------------
extern "C" void kernel_launch(void* const* d_in, const int* in_sizes, int n_in,
                              void* d_out, int out_size)
{
    const float* x  = (const float*)d_in[0];
    const float* Wq = (const float*)d_in[1];
    const float* Wk = (const float*)d_in[2];
    const float* Wv = (const float*)d_in[3];
    const float* Wu = (const float*)d_in[4];
    const float* bu = (const float*)d_in[5];
    float* out = (float*)d_out;

    cvt_kernel<<<dim3(MTOT, 5), 256>>>(x, Wq, Wk, Wv, Wu);

    cudaFuncSetAttribute(qkv_mma, cudaFuncAttributeMaxDynamicSharedMemorySize, SMEM_MMA);
    qkv_mma<<<dim3(KD / 128, MTOT / 128, 3), 256, SMEM_MMA>>>();

    cudaFuncSetAttribute(attn_mma, cudaFuncAttributeMaxDynamicSharedMemorySize, ATT_SMEM);
    attn_mma<<<dim3(TT / 64, NH, BB), 128, ATT_SMEM>>>();

    cudaFuncSetAttribute(out_mma, cudaFuncAttributeMaxDynamicSharedMemorySize, SMEM_MMA);
    out_mma<<<dim3(KD / 128, MTOT / 128), 256, SMEM_MMA>>>(bu, out);
}

// round 15
// speedup vs baseline: 1.0442x; 1.0442x over previous
#include <cuda_runtime.h>
#include <cuda_fp16.h>
#include <math_constants.h>
#include <cstdint>

#define BB   2
#define TT   2048
#define KD   1024
#define NH   16
#define HD   64
#define MTOT (BB*TT)

// ---------------- scratch (__device__ globals, allocation-free) -------------
__device__ __half g_xh [(size_t)MTOT * KD];
__device__ __half g_wqh[(size_t)KD   * KD];
__device__ __half g_wkh[(size_t)KD   * KD];
__device__ __half g_wvh[(size_t)KD   * KD];
__device__ __half g_wuh[(size_t)KD   * KD];
__device__ __half g_qh [(size_t)MTOT * KD];
__device__ __half g_kh [(size_t)MTOT * KD];
__device__ __half g_vh [(size_t)MTOT * KD];
__device__ __half g_oh [(size_t)MTOT * KD];

// ---------------- helpers ----------------------------------------------------
__device__ __forceinline__ uint32_t smem_u32(const void* p) {
    uint32_t a;
    asm("{ .reg .u64 t; cvta.to.shared.u64 t, %1; cvt.u32.u64 %0, t; }"
        : "=r"(a) : "l"(p));
    return a;
}
__device__ __forceinline__ void cp16(uint32_t dst, const void* src) {
    asm volatile("cp.async.cg.shared.global [%0], [%1], 16;" :: "r"(dst), "l"(src));
}
__device__ __forceinline__ void cp_commit() {
    asm volatile("cp.async.commit_group;" ::: "memory");
}
template <int N>
__device__ __forceinline__ void cp_wait() {
    asm volatile("cp.async.wait_group %0;" :: "n"(N) : "memory");
}
__device__ __forceinline__ void ldm_x4(uint32_t* r, uint32_t addr) {
    asm volatile("ldmatrix.sync.aligned.m8n8.x4.shared.b16 {%0,%1,%2,%3}, [%4];"
                 : "=r"(r[0]), "=r"(r[1]), "=r"(r[2]), "=r"(r[3]) : "r"(addr));
}
__device__ __forceinline__ void ldm_x4_t(uint32_t* r, uint32_t addr) {
    asm volatile("ldmatrix.sync.aligned.m8n8.x4.trans.shared.b16 {%0,%1,%2,%3}, [%4];"
                 : "=r"(r[0]), "=r"(r[1]), "=r"(r[2]), "=r"(r[3]) : "r"(addr));
}
__device__ __forceinline__ void mma_f16(float* c, const uint32_t* a, const uint32_t* b) {
    asm volatile(
        "mma.sync.aligned.m16n8k16.row.col.f32.f16.f16.f32 "
        "{%0,%1,%2,%3}, {%4,%5,%6,%7}, {%8,%9}, {%0,%1,%2,%3};"
        : "+f"(c[0]), "+f"(c[1]), "+f"(c[2]), "+f"(c[3])
        : "r"(a[0]), "r"(a[1]), "r"(a[2]), "r"(a[3]), "r"(b[0]), "r"(b[1]));
}
// fp16-accumulator MMA (C/D fragments are 2 regs of packed half2)
__device__ __forceinline__ void mma_f16acc(uint32_t* c, const uint32_t* a, const uint32_t* b) {
    asm volatile(
        "mma.sync.aligned.m16n8k16.row.col.f16.f16.f16.f16 "
        "{%0,%1}, {%2,%3,%4,%5}, {%6,%7}, {%0,%1};"
        : "+r"(c[0]), "+r"(c[1])
        : "r"(a[0]), "r"(a[1]), "r"(a[2]), "r"(a[3]), "r"(b[0]), "r"(b[1]));
}
__device__ __forceinline__ uint32_t pack_h2(float a, float b) {
    __half2 h = __floats2half2_rn(a, b);
    return *(uint32_t*)&h;
}
__device__ __forceinline__ uint32_t sw128(uint32_t off) {
    return off ^ ((off >> 3) & 0x70);
}

// ---------------- fused fp32 -> fp16 conversion ------------------------------
__global__ void cvt_kernel(const float* __restrict__ x,  const float* __restrict__ wq,
                           const float* __restrict__ wk, const float* __restrict__ wv,
                           const float* __restrict__ wu)
{
    const int which = blockIdx.y;
    const float* in;
    __half* out;
    int rows;
    switch (which) {
        case 0: in = x;  out = g_xh;  rows = MTOT; break;
        case 1: in = wq; out = g_wqh; rows = KD;   break;
        case 2: in = wk; out = g_wkh; rows = KD;   break;
        case 3: in = wv; out = g_wvh; rows = KD;   break;
        default: in = wu; out = g_wuh; rows = KD;  break;
    }
    int r = blockIdx.x;
    if (r >= rows) return;
    int c = threadIdx.x * 4;
    float4 a = *(const float4*)(in + (size_t)r * KD + c);
    uint2 o;
    o.x = pack_h2(a.x, a.y);
    o.y = pack_h2(a.z, a.w);
    *(uint2*)(out + (size_t)r * KD + c) = o;
}

// ---------------- mma.sync fp16 GEMM: 128x128 tile, BK=64, 3-stage (R8) ------
#define GROW   144                       // bytes per smem row (64 fp16 + 8 pad)
#define TILE_B (128 * GROW)              // 18432 per matrix tile
#define STAGE_ALL (2 * TILE_B)           // 36864 per stage (A+B)
#define SMEM_MMA (3 * STAGE_ALL)         // 110592

__device__ __forceinline__ void load_stage(
    const __half* __restrict__ Ag, const __half* __restrict__ Wg,
    uint32_t sA, uint32_t sB, int tid)
{
#pragma unroll
    for (int i = 0; i < 4; i++) {
        int c = tid + i * 256;           // 0..1023
        int r = c >> 3;                  // 0..127
        int q = c & 7;                   // 16B chunk
        cp16(sA + r * GROW + q * 16, Ag + (size_t)r * KD + q * 8);
        cp16(sB + r * GROW + q * 16, Wg + (size_t)r * KD + q * 8);
    }
}

__device__ __forceinline__ void tgemm_mma(
    const __half* __restrict__ A2, const __half* __restrict__ W2,
    float scale, int mode,
    float* __restrict__ Cf, const float* __restrict__ bias,
    __half* __restrict__ Ch)
{
    extern __shared__ char sm[];
    const uint32_t smb = smem_u32(sm);
    const int tid    = threadIdx.x;
    const int lane   = tid & 31;
    const int wid    = tid >> 5;
    const int warp_m = wid & 1;
    const int warp_n = wid >> 1;
    const int m0     = blockIdx.y * 128;
    const int n0     = blockIdx.x * 128;

    const __half* Abase = A2 + (size_t)m0 * KD;
    const __half* Wbase = W2 + (size_t)n0 * KD;

    float acc[4][4][4];
#pragma unroll
    for (int i = 0; i < 4; i++)
#pragma unroll
        for (int j = 0; j < 4; j++)
#pragma unroll
            for (int r = 0; r < 4; r++) acc[i][j][r] = 0.f;

    const int NIT = 16;                  // 1024 / 64

    load_stage(Abase,      Wbase,      smb,             smb + TILE_B,             tid);
    cp_commit();
    load_stage(Abase + 64, Wbase + 64, smb + STAGE_ALL, smb + STAGE_ALL + TILE_B, tid);
    cp_commit();

    const int a_row = (lane & 15);
    const int a_col = (lane >> 4) << 3;
    const int b_row = ((lane >> 4) << 3) + (lane & 7);
    const int b_col = ((lane >> 3) & 1) << 3;

    for (int it = 0; it < NIT; it++) {
        if (it == NIT - 1) cp_wait<0>(); else cp_wait<1>();
        __syncthreads();
        if (it + 2 < NIT) {
            uint32_t sl = smb + ((it + 2) % 3) * STAGE_ALL;
            load_stage(Abase + (it + 2) * 64, Wbase + (it + 2) * 64,
                       sl, sl + TILE_B, tid);
            cp_commit();
        }

        const uint32_t sA = smb + (it % 3) * STAGE_ALL;
        const uint32_t sB = sA + TILE_B;

#pragma unroll
        for (int ks = 0; ks < 4; ks++) {
            uint32_t a[4][4], b[2][4];
#pragma unroll
            for (int mi = 0; mi < 4; mi++)
                ldm_x4(a[mi], sA + (warp_m * 64 + mi * 16 + a_row) * GROW
                              + (ks * 16 + a_col) * 2);
#pragma unroll
            for (int ni = 0; ni < 2; ni++)
                ldm_x4(b[ni], sB + (warp_n * 32 + ni * 16 + b_row) * GROW
                              + (ks * 16 + b_col) * 2);
#pragma unroll
            for (int mi = 0; mi < 4; mi++)
#pragma unroll
                for (int nj = 0; nj < 4; nj++)
                    mma_f16(acc[mi][nj], a[mi], &b[nj >> 1][(nj & 1) * 2]);
        }
    }

#pragma unroll
    for (int mi = 0; mi < 4; mi++) {
#pragma unroll
        for (int nj = 0; nj < 4; nj++) {
            int row = m0 + warp_m * 64 + mi * 16 + (lane >> 2);
            int col = n0 + warp_n * 32 + nj * 8 + (lane & 3) * 2;
            float v00 = acc[mi][nj][0] * scale, v01 = acc[mi][nj][1] * scale;
            float v10 = acc[mi][nj][2] * scale, v11 = acc[mi][nj][3] * scale;
            if (mode == 0) {
                float b0 = bias[col], b1 = bias[col + 1];
                *(float2*)(Cf + (size_t)row * KD + col)       = make_float2(v00 + b0, v01 + b1);
                *(float2*)(Cf + (size_t)(row + 8) * KD + col) = make_float2(v10 + b0, v11 + b1);
            } else {
                *(uint32_t*)(Ch + (size_t)row * KD + col)       = pack_h2(v00, v01);
                *(uint32_t*)(Ch + (size_t)(row + 8) * KD + col) = pack_h2(v10, v11);
            }
        }
    }
}

// q/k scale: 1024^(-1/4) * sqrt(log2(e))  -> S lands directly in log2 domain
#define QK_SCALE 0.2123296923175822f

__global__ __launch_bounds__(256, 2) void qkv_mma() {
    if (blockIdx.z == 0)
        tgemm_mma(g_xh, g_wqh, QK_SCALE, 1, nullptr, nullptr, g_qh);
    else if (blockIdx.z == 1)
        tgemm_mma(g_xh, g_wkh, QK_SCALE, 1, nullptr, nullptr, g_kh);
    else
        tgemm_mma(g_xh, g_wvh, 1.0f, 1, nullptr, nullptr, g_vh);
}

__global__ __launch_bounds__(256, 2) void out_mma(const float* __restrict__ bu,
                                                  float* __restrict__ out) {
    tgemm_mma(g_oh, g_wuh, 1.0f, 0, out, bu, nullptr);
}

// ---------------- tensorized flash attention (fp16) ---------------------------
// CTA: Br=128 q-rows x (head, batch). 4 warps x 32 ROWS each, Bc=64, 3-stage.
// 32 rows/warp doubles MMAs per K/V ldmatrix fragment -> halves smem-crossbar
// traffic per unit work (the R11 binding resource). 128 threads @ occ 2 gives
// a 256-reg cap (no R14-style spills). Numerics identical to R11: f16-acc S in
// log2 domain, no running max, in-place h2exp2, l from rounded P.
#define AKV_STAGE 16384                         // K 8K + V 8K
#define ATT_SMEM  (16384 + 3 * AKV_STAGE)       // 65536

__device__ __forceinline__ void attn_load_kv(const __half* Kg, const __half* Vg,
                                             size_t base, uint32_t sK, int tid)
{
#pragma unroll
    for (int i = 0; i < 4; i++) {
        int c = tid + i * 128, r = c >> 3, q = c & 7;   // 64 rows x 8 chunks
        uint32_t so = sw128(r * 128 + q * 16);
        size_t   go = (base + r) * KD + q * 8;
        cp16(sK + so,        Kg + go);
        cp16(sK + 8192 + so, Vg + go);
    }
}

__global__ __launch_bounds__(128, 2) void attn_mma()
{
    extern __shared__ char sm[];
    const uint32_t smb = smem_u32(sm);
    const int tid = threadIdx.x, lane = tid & 31, w = tid >> 5;
    const int qb = blockIdx.x, h = blockIdx.y, b = blockIdx.z;

    const __half* Qg = g_qh + (size_t)(b * TT + qb * 128) * KD + h * HD;
    const __half* Kg = g_kh + (size_t)(b * TT) * KD + h * HD;
    const __half* Vg = g_vh + (size_t)(b * TT) * KD + h * HD;

    const uint32_t sQ = smb;

    // Q: 128 rows x 8 chunks = 1024 (grouped with stage-0 K/V commit)
#pragma unroll
    for (int i = 0; i < 8; i++) {
        int c = tid + i * 128, r = c >> 3, q = c & 7;
        cp16(sQ + sw128(r * 128 + q * 16), Qg + (size_t)r * KD + q * 8);
    }
    attn_load_kv(Kg, Vg, 0,  smb + 16384,             tid);
    cp_commit();
    attn_load_kv(Kg, Vg, 64, smb + 16384 + AKV_STAGE, tid);
    cp_commit();

    float oacc[2][8][4];
#pragma unroll
    for (int mi = 0; mi < 2; mi++)
#pragma unroll
        for (int f = 0; f < 8; f++)
#pragma unroll
            for (int r = 0; r < 4; r++) oacc[mi][f][r] = 0.f;
    float lsum[2][2] = {{0.f, 0.f}, {0.f, 0.f}};
    uint32_t qa[2][4][4];

    const int NTILE = TT / 64;           // 32

    for (int jb = 0; jb < NTILE; jb++) {
        if (jb == NTILE - 1) cp_wait<0>(); else cp_wait<1>();
        __syncthreads();

        if (jb + 2 < NTILE) {
            attn_load_kv(Kg, Vg, (size_t)(jb + 2) * 64,
                         smb + 16384 + ((jb + 2) % 3) * AKV_STAGE, tid);
            cp_commit();
        }

        if (jb == 0) {
#pragma unroll
            for (int mi = 0; mi < 2; mi++)
#pragma unroll
                for (int ks = 0; ks < 4; ks++) {
                    int ar = w * 32 + mi * 16 + (lane & 15);
                    int ac = ks * 16 + ((lane >> 4) << 3);
                    ldm_x4(qa[mi][ks], sQ + sw128(ar * 128 + ac * 2));
                }
        }

        const uint32_t sK = smb + 16384 + (jb % 3) * AKV_STAGE;
        const uint32_t sV = sK + 8192;

        // ---- S = Q * K^T, f16 accumulators: 32 rows x 64 cols per warp ----
        uint32_t sacc[2][8][2];
#pragma unroll
        for (int mi = 0; mi < 2; mi++)
#pragma unroll
            for (int j = 0; j < 8; j++) { sacc[mi][j][0] = 0u; sacc[mi][j][1] = 0u; }

#pragma unroll
        for (int ks = 0; ks < 4; ks++) {
#pragma unroll
            for (int jn = 0; jn < 4; jn++) {
                uint32_t kb[4];
                int br = jn * 16 + ((lane >> 4) << 3) + (lane & 7);
                int bc = ks * 16 + (((lane >> 3) & 1) << 3);
                ldm_x4(kb, sK + sw128(br * 128 + bc * 2));
#pragma unroll
                for (int mi = 0; mi < 2; mi++) {
                    mma_f16acc(sacc[mi][2 * jn],     qa[mi][ks], kb);
                    mma_f16acc(sacc[mi][2 * jn + 1], qa[mi][ks], kb + 2);
                }
            }
        }

        // ---- P = exp2(S) in place; l summed from the rounded P ----
        uint32_t ph[2][4][4];
#pragma unroll
        for (int mi = 0; mi < 2; mi++) {
            __half2 sA = __float2half2_rn(0.f), sB = sA;
#pragma unroll
            for (int j = 0; j < 8; j++) {
                __half2 pA = h2exp2(*(__half2*)&sacc[mi][j][0]);   // row lane/4
                __half2 pB = h2exp2(*(__half2*)&sacc[mi][j][1]);   // row lane/4 + 8
                sA = __hadd2(sA, pA);
                sB = __hadd2(sB, pB);
                int kv = j >> 1, o = (j & 1) * 2;
                ph[mi][kv][o]     = *(uint32_t*)&pA;
                ph[mi][kv][o + 1] = *(uint32_t*)&pB;
            }
            float2 fA = __half22float2(sA), fB = __half22float2(sB);
            lsum[mi][0] += fA.x + fA.y;
            lsum[mi][1] += fB.x + fB.y;
        }

        // ---- O += P * V (fp32 accumulators) ----
#pragma unroll
        for (int kv = 0; kv < 4; kv++) {
#pragma unroll
            for (int nb = 0; nb < 4; nb++) {
                uint32_t vb[4];
                int vr = kv * 16 + (((lane >> 3) & 1) << 3) + (lane & 7);
                int vc = nb * 16 + ((lane >> 4) << 3);
                ldm_x4_t(vb, sV + sw128(vr * 128 + vc * 2));
#pragma unroll
                for (int mi = 0; mi < 2; mi++) {
                    mma_f16(oacc[mi][2 * nb],     ph[mi][kv], vb);
                    mma_f16(oacc[mi][2 * nb + 1], ph[mi][kv], vb + 2);
                }
            }
        }
    }

    // finalize + write
#pragma unroll
    for (int mi = 0; mi < 2; mi++) {
        float l0 = lsum[mi][0], l1 = lsum[mi][1];
        l0 += __shfl_xor_sync(0xffffffffu, l0, 1);
        l0 += __shfl_xor_sync(0xffffffffu, l0, 2);
        l1 += __shfl_xor_sync(0xffffffffu, l1, 1);
        l1 += __shfl_xor_sync(0xffffffffu, l1, 2);
        float inv0 = 1.f / l0, inv1 = 1.f / l1;

        size_t r0g = (size_t)(b * TT + qb * 128 + w * 32 + mi * 16 + (lane >> 2));
        size_t r1g = r0g + 8;
        int colb = h * HD + 2 * (lane & 3);
#pragma unroll
        for (int f = 0; f < 8; f++) {
            int col = colb + f * 8;
            *(uint32_t*)(g_oh + r0g * KD + col) =
                pack_h2(oacc[mi][f][0] * inv0, oacc[mi][f][1] * inv0);
            *(uint32_t*)(g_oh + r1g * KD + col) =
                pack_h2(oacc[mi][f][2] * inv1, oacc[mi][f][3] * inv1);
        }
    }
}

// ---------------------------------------------------------------------------
extern "C" void kernel_launch(void* const* d_in, const int* in_sizes, int n_in,
                              void* d_out, int out_size)
{
    const float* x  = (const float*)d_in[0];
    const float* Wq = (const float*)d_in[1];
    const float* Wk = (const float*)d_in[2];
    const float* Wv = (const float*)d_in[3];
    const float* Wu = (const float*)d_in[4];
    const float* bu = (const float*)d_in[5];
    float* out = (float*)d_out;

    cvt_kernel<<<dim3(MTOT, 5), 256>>>(x, Wq, Wk, Wv, Wu);

    cudaFuncSetAttribute(qkv_mma, cudaFuncAttributeMaxDynamicSharedMemorySize, SMEM_MMA);
    qkv_mma<<<dim3(KD / 128, MTOT / 128, 3), 256, SMEM_MMA>>>();

    cudaFuncSetAttribute(attn_mma, cudaFuncAttributeMaxDynamicSharedMemorySize, ATT_SMEM);
    attn_mma<<<dim3(TT / 128, NH, BB), 128, ATT_SMEM>>>();

    cudaFuncSetAttribute(out_mma, cudaFuncAttributeMaxDynamicSharedMemorySize, SMEM_MMA);
    out_mma<<<dim3(KD / 128, MTOT / 128), 256, SMEM_MMA>>>(bu, out);
}

// round 16
// speedup vs baseline: 1.0923x; 1.0461x over previous
#include <cuda_runtime.h>
#include <cuda_fp16.h>
#include <math_constants.h>
#include <cstdint>

#define BB   2
#define TT   2048
#define KD   1024
#define NH   16
#define HD   64
#define MTOT (BB*TT)

// ---------------- scratch (__device__ globals, allocation-free) -------------
__device__ __half g_xh [(size_t)MTOT * KD];
__device__ __half g_wqh[(size_t)KD   * KD];
__device__ __half g_wkh[(size_t)KD   * KD];
__device__ __half g_wvh[(size_t)KD   * KD];
__device__ __half g_wuh[(size_t)KD   * KD];
__device__ __half g_qh [(size_t)MTOT * KD];
__device__ __half g_kh [(size_t)MTOT * KD];
__device__ __half g_vh [(size_t)MTOT * KD];
__device__ __half g_oh [(size_t)MTOT * KD];

// ---------------- helpers ----------------------------------------------------
__device__ __forceinline__ uint32_t smem_u32(const void* p) {
    uint32_t a;
    asm("{ .reg .u64 t; cvta.to.shared.u64 t, %1; cvt.u32.u64 %0, t; }"
        : "=r"(a) : "l"(p));
    return a;
}
__device__ __forceinline__ void cp16(uint32_t dst, const void* src) {
    asm volatile("cp.async.cg.shared.global [%0], [%1], 16;" :: "r"(dst), "l"(src));
}
__device__ __forceinline__ void cp_commit() {
    asm volatile("cp.async.commit_group;" ::: "memory");
}
template <int N>
__device__ __forceinline__ void cp_wait() {
    asm volatile("cp.async.wait_group %0;" :: "n"(N) : "memory");
}
__device__ __forceinline__ void ldm_x4(uint32_t* r, uint32_t addr) {
    asm volatile("ldmatrix.sync.aligned.m8n8.x4.shared.b16 {%0,%1,%2,%3}, [%4];"
                 : "=r"(r[0]), "=r"(r[1]), "=r"(r[2]), "=r"(r[3]) : "r"(addr));
}
__device__ __forceinline__ void ldm_x4_t(uint32_t* r, uint32_t addr) {
    asm volatile("ldmatrix.sync.aligned.m8n8.x4.trans.shared.b16 {%0,%1,%2,%3}, [%4];"
                 : "=r"(r[0]), "=r"(r[1]), "=r"(r[2]), "=r"(r[3]) : "r"(addr));
}
__device__ __forceinline__ void mma_f16(float* c, const uint32_t* a, const uint32_t* b) {
    asm volatile(
        "mma.sync.aligned.m16n8k16.row.col.f32.f16.f16.f32 "
        "{%0,%1,%2,%3}, {%4,%5,%6,%7}, {%8,%9}, {%0,%1,%2,%3};"
        : "+f"(c[0]), "+f"(c[1]), "+f"(c[2]), "+f"(c[3])
        : "r"(a[0]), "r"(a[1]), "r"(a[2]), "r"(a[3]), "r"(b[0]), "r"(b[1]));
}
// fp16-accumulator MMA (C/D fragments are 2 regs of packed half2)
__device__ __forceinline__ void mma_f16acc(uint32_t* c, const uint32_t* a, const uint32_t* b) {
    asm volatile(
        "mma.sync.aligned.m16n8k16.row.col.f16.f16.f16.f16 "
        "{%0,%1}, {%2,%3,%4,%5}, {%6,%7}, {%0,%1};"
        : "+r"(c[0]), "+r"(c[1])
        : "r"(a[0]), "r"(a[1]), "r"(a[2]), "r"(a[3]), "r"(b[0]), "r"(b[1]));
}
__device__ __forceinline__ uint32_t pack_h2(float a, float b) {
    __half2 h = __floats2half2_rn(a, b);
    return *(uint32_t*)&h;
}
__device__ __forceinline__ uint32_t sw128(uint32_t off) {
    return off ^ ((off >> 3) & 0x70);
}

// ---------------- fused fp32 -> fp16 conversion (exact linear grid) ----------
__global__ void cvt_kernel(const float* __restrict__ x,  const float* __restrict__ wq,
                           const float* __restrict__ wk, const float* __restrict__ wv,
                           const float* __restrict__ wu)
{
    int gid = blockIdx.x;
    const float* in;
    __half* out;
    int r;
    if (gid < MTOT) {
        in = x; out = g_xh; r = gid;
    } else {
        int t = gid - MTOT;
        int which = t >> 10;             // t / KD
        r = t & (KD - 1);                // t % KD
        switch (which) {
            case 0: in = wq; out = g_wqh; break;
            case 1: in = wk; out = g_wkh; break;
            case 2: in = wv; out = g_wvh; break;
            default: in = wu; out = g_wuh; break;
        }
    }
    int c = threadIdx.x * 4;
    float4 a = *(const float4*)(in + (size_t)r * KD + c);
    uint2 o;
    o.x = pack_h2(a.x, a.y);
    o.y = pack_h2(a.z, a.w);
    *(uint2*)(out + (size_t)r * KD + c) = o;
}

// ---------------- mma.sync fp16 GEMM: 128x128 tile, BK=64, 3-stage (R8) ------
#define GROW   144                       // bytes per smem row (64 fp16 + 8 pad)
#define TILE_B (128 * GROW)              // 18432 per matrix tile
#define STAGE_ALL (2 * TILE_B)           // 36864 per stage (A+B)
#define SMEM_MMA (3 * STAGE_ALL)         // 110592

__device__ __forceinline__ void load_stage(
    const __half* __restrict__ Ag, const __half* __restrict__ Wg,
    uint32_t sA, uint32_t sB, int tid)
{
#pragma unroll
    for (int i = 0; i < 4; i++) {
        int c = tid + i * 256;           // 0..1023
        int r = c >> 3;                  // 0..127
        int q = c & 7;                   // 16B chunk
        cp16(sA + r * GROW + q * 16, Ag + (size_t)r * KD + q * 8);
        cp16(sB + r * GROW + q * 16, Wg + (size_t)r * KD + q * 8);
    }
}

__device__ __forceinline__ void tgemm_mma(
    const __half* __restrict__ A2, const __half* __restrict__ W2,
    float scale, int mode,
    float* __restrict__ Cf, const float* __restrict__ bias,
    __half* __restrict__ Ch)
{
    extern __shared__ char sm[];
    const uint32_t smb = smem_u32(sm);
    const int tid    = threadIdx.x;
    const int lane   = tid & 31;
    const int wid    = tid >> 5;
    const int warp_m = wid & 1;
    const int warp_n = wid >> 1;
    const int m0     = blockIdx.y * 128;
    const int n0     = blockIdx.x * 128;

    const __half* Abase = A2 + (size_t)m0 * KD;
    const __half* Wbase = W2 + (size_t)n0 * KD;

    float acc[4][4][4];
#pragma unroll
    for (int i = 0; i < 4; i++)
#pragma unroll
        for (int j = 0; j < 4; j++)
#pragma unroll
            for (int r = 0; r < 4; r++) acc[i][j][r] = 0.f;

    const int NIT = 16;                  // 1024 / 64

    load_stage(Abase,      Wbase,      smb,             smb + TILE_B,             tid);
    cp_commit();
    load_stage(Abase + 64, Wbase + 64, smb + STAGE_ALL, smb + STAGE_ALL + TILE_B, tid);
    cp_commit();

    const int a_row = (lane & 15);
    const int a_col = (lane >> 4) << 3;
    const int b_row = ((lane >> 4) << 3) + (lane & 7);
    const int b_col = ((lane >> 3) & 1) << 3;

    for (int it = 0; it < NIT; it++) {
        if (it == NIT - 1) cp_wait<0>(); else cp_wait<1>();
        __syncthreads();
        if (it + 2 < NIT) {
            uint32_t sl = smb + ((it + 2) % 3) * STAGE_ALL;
            load_stage(Abase + (it + 2) * 64, Wbase + (it + 2) * 64,
                       sl, sl + TILE_B, tid);
            cp_commit();
        }

        const uint32_t sA = smb + (it % 3) * STAGE_ALL;
        const uint32_t sB = sA + TILE_B;

#pragma unroll
        for (int ks = 0; ks < 4; ks++) {
            uint32_t a[4][4], b[2][4];
#pragma unroll
            for (int mi = 0; mi < 4; mi++)
                ldm_x4(a[mi], sA + (warp_m * 64 + mi * 16 + a_row) * GROW
                              + (ks * 16 + a_col) * 2);
#pragma unroll
            for (int ni = 0; ni < 2; ni++)
                ldm_x4(b[ni], sB + (warp_n * 32 + ni * 16 + b_row) * GROW
                              + (ks * 16 + b_col) * 2);
#pragma unroll
            for (int mi = 0; mi < 4; mi++)
#pragma unroll
                for (int nj = 0; nj < 4; nj++)
                    mma_f16(acc[mi][nj], a[mi], &b[nj >> 1][(nj & 1) * 2]);
        }
    }

#pragma unroll
    for (int mi = 0; mi < 4; mi++) {
#pragma unroll
        for (int nj = 0; nj < 4; nj++) {
            int row = m0 + warp_m * 64 + mi * 16 + (lane >> 2);
            int col = n0 + warp_n * 32 + nj * 8 + (lane & 3) * 2;
            float v00 = acc[mi][nj][0] * scale, v01 = acc[mi][nj][1] * scale;
            float v10 = acc[mi][nj][2] * scale, v11 = acc[mi][nj][3] * scale;
            if (mode == 0) {
                float b0 = bias[col], b1 = bias[col + 1];
                *(float2*)(Cf + (size_t)row * KD + col)       = make_float2(v00 + b0, v01 + b1);
                *(float2*)(Cf + (size_t)(row + 8) * KD + col) = make_float2(v10 + b0, v11 + b1);
            } else {
                *(uint32_t*)(Ch + (size_t)row * KD + col)       = pack_h2(v00, v01);
                *(uint32_t*)(Ch + (size_t)(row + 8) * KD + col) = pack_h2(v10, v11);
            }
        }
    }
}

// q/k scale: 1024^(-1/4) * sqrt(log2(e))  -> S lands directly in log2 domain
#define QK_SCALE 0.2123296923175822f

__global__ __launch_bounds__(256, 2) void qkv_mma() {
    if (blockIdx.z == 0)
        tgemm_mma(g_xh, g_wqh, QK_SCALE, 1, nullptr, nullptr, g_qh);
    else if (blockIdx.z == 1)
        tgemm_mma(g_xh, g_wkh, QK_SCALE, 1, nullptr, nullptr, g_kh);
    else
        tgemm_mma(g_xh, g_wvh, 1.0f, 1, nullptr, nullptr, g_vh);
}

__global__ __launch_bounds__(256, 2) void out_mma(const float* __restrict__ bu,
                                                  float* __restrict__ out) {
    tgemm_mma(g_oh, g_wuh, 1.0f, 0, out, bu, nullptr);
}

// ---------------- tensorized flash attention (fp16, R11 champion) ------------
// CTA: 64 q-rows x (head, batch). 4 warps, 16 rows each, Bc = 128, 3-stage,
// 2 CTAs/SM. No running max (log2-domain logits; max cancels in p/l).
// S uses f16-acc mma whose C fragment == PV A fragment (h2exp2 in-place).
#define AKV_STAGE 32768                         // K 16K + V 16K
#define ATT_SMEM  (8192 + 3 * AKV_STAGE)        // 106496 -> 2 CTAs/SM

__device__ __forceinline__ void attn_load_kv(const __half* Kg, const __half* Vg,
                                             size_t base, uint32_t sK, int tid)
{
#pragma unroll
    for (int i = 0; i < 8; i++) {
        int c = tid + i * 128, r = c >> 3, q = c & 7;   // 128 rows x 8 chunks
        uint32_t so = sw128(r * 128 + q * 16);
        size_t   go = (base + r) * KD + q * 8;
        cp16(sK + so,         Kg + go);
        cp16(sK + 16384 + so, Vg + go);
    }
}

__global__ __launch_bounds__(128, 2) void attn_mma()
{
    extern __shared__ char sm[];
    const uint32_t smb = smem_u32(sm);
    const int tid = threadIdx.x, lane = tid & 31, w = tid >> 5;
    const int qb = blockIdx.x, h = blockIdx.y, b = blockIdx.z;

    const __half* Qg = g_qh + (size_t)(b * TT + qb * 64) * KD + h * HD;
    const __half* Kg = g_kh + (size_t)(b * TT) * KD + h * HD;
    const __half* Vg = g_vh + (size_t)(b * TT) * KD + h * HD;

    const uint32_t sQ = smb;

    // Q: 64 rows x 8 chunks = 512
#pragma unroll
    for (int i = 0; i < 4; i++) {
        int c = tid + i * 128, r = c >> 3, q = c & 7;
        cp16(sQ + sw128(r * 128 + q * 16), Qg + (size_t)r * KD + q * 8);
    }
    attn_load_kv(Kg, Vg, 0,   smb + 8192,             tid);
    cp_commit();
    attn_load_kv(Kg, Vg, 128, smb + 8192 + AKV_STAGE, tid);
    cp_commit();

    float oacc[8][4];
#pragma unroll
    for (int f = 0; f < 8; f++)
#pragma unroll
        for (int r = 0; r < 4; r++) oacc[f][r] = 0.f;
    float l0 = 0.f, l1 = 0.f;
    uint32_t qa[4][4];

    const int NTILE = TT / 128;          // 16

    for (int jb = 0; jb < NTILE; jb++) {
        if (jb == NTILE - 1) cp_wait<0>(); else cp_wait<1>();
        __syncthreads();

        if (jb + 2 < NTILE) {
            attn_load_kv(Kg, Vg, (size_t)(jb + 2) * 128,
                         smb + 8192 + ((jb + 2) % 3) * AKV_STAGE, tid);
            cp_commit();
        }

        if (jb == 0) {
#pragma unroll
            for (int ks = 0; ks < 4; ks++) {
                int ar = w * 16 + (lane & 15);
                int ac = ks * 16 + ((lane >> 4) << 3);
                ldm_x4(qa[ks], sQ + sw128(ar * 128 + ac * 2));
            }
        }

        const uint32_t sK = smb + 8192 + (jb % 3) * AKV_STAGE;
        const uint32_t sV = sK + 16384;

        // ---- S = Q * K^T, f16 accumulators (log2-domain logits) ----
        uint32_t sacc[16][2];
#pragma unroll
        for (int j = 0; j < 16; j++) { sacc[j][0] = 0u; sacc[j][1] = 0u; }

#pragma unroll
        for (int ks = 0; ks < 4; ks++) {
#pragma unroll
            for (int jn = 0; jn < 8; jn++) {
                uint32_t kb[4];
                int br = jn * 16 + ((lane >> 4) << 3) + (lane & 7);
                int bc = ks * 16 + (((lane >> 3) & 1) << 3);
                ldm_x4(kb, sK + sw128(br * 128 + bc * 2));
                mma_f16acc(sacc[2 * jn],     qa[ks], kb);
                mma_f16acc(sacc[2 * jn + 1], qa[ks], kb + 2);
            }
        }

        // ---- P = exp2(S) directly on the f16 accumulator registers ----
        uint32_t ph[8][4];
        __half2 sA0 = __float2half2_rn(0.f), sA1 = sA0;
        __half2 sB0 = sA0, sB1 = sA0;
#pragma unroll
        for (int j = 0; j < 16; j++) {
            __half2 pA = h2exp2(*(__half2*)&sacc[j][0]);   // row lane/4
            __half2 pB = h2exp2(*(__half2*)&sacc[j][1]);   // row lane/4 + 8
            if (j & 1) { sA1 = __hadd2(sA1, pA); sB1 = __hadd2(sB1, pB); }
            else       { sA0 = __hadd2(sA0, pA); sB0 = __hadd2(sB0, pB); }
            int kv = j >> 1, o = (j & 1) * 2;
            ph[kv][o]     = *(uint32_t*)&pA;
            ph[kv][o + 1] = *(uint32_t*)&pB;
        }
        {
            float2 fA0 = __half22float2(sA0), fA1 = __half22float2(sA1);
            float2 fB0 = __half22float2(sB0), fB1 = __half22float2(sB1);
            l0 += (fA0.x + fA0.y) + (fA1.x + fA1.y);
            l1 += (fB0.x + fB0.y) + (fB1.x + fB1.y);
        }

        // ---- O += P * V (fp32 accumulators) ----
#pragma unroll
        for (int kv = 0; kv < 8; kv++) {
#pragma unroll
            for (int nb = 0; nb < 4; nb++) {
                uint32_t vb[4];
                int vr = kv * 16 + (((lane >> 3) & 1) << 3) + (lane & 7);
                int vc = nb * 16 + ((lane >> 4) << 3);
                ldm_x4_t(vb, sV + sw128(vr * 128 + vc * 2));
                mma_f16(oacc[2 * nb],     ph[kv], vb);
                mma_f16(oacc[2 * nb + 1], ph[kv], vb + 2);
            }
        }
    }

    l0 += __shfl_xor_sync(0xffffffffu, l0, 1);
    l0 += __shfl_xor_sync(0xffffffffu, l0, 2);
    l1 += __shfl_xor_sync(0xffffffffu, l1, 1);
    l1 += __shfl_xor_sync(0xffffffffu, l1, 2);
    float inv0 = 1.f / l0, inv1 = 1.f / l1;

    size_t r0g = (size_t)(b * TT + qb * 64 + w * 16 + (lane >> 2));
    size_t r1g = r0g + 8;
    int colb = h * HD + 2 * (lane & 3);
#pragma unroll
    for (int f = 0; f < 8; f++) {
        int col = colb + f * 8;
        *(uint32_t*)(g_oh + r0g * KD + col) = pack_h2(oacc[f][0] * inv0, oacc[f][1] * inv0);
        *(uint32_t*)(g_oh + r1g * KD + col) = pack_h2(oacc[f][2] * inv1, oacc[f][3] * inv1);
    }
}

// ---------------------------------------------------------------------------
extern "C" void kernel_launch(void* const* d_in, const int* in_sizes, int n_in,
                              void* d_out, int out_size)
{
    const float* x  = (const float*)d_in[0];
    const float* Wq = (const float*)d_in[1];
    const float* Wk = (const float*)d_in[2];
    const float* Wv = (const float*)d_in[3];
    const float* Wu = (const float*)d_in[4];
    const float* bu = (const float*)d_in[5];
    float* out = (float*)d_out;

    cvt_kernel<<<MTOT + 4 * KD, 256>>>(x, Wq, Wk, Wv, Wu);

    cudaFuncSetAttribute(qkv_mma, cudaFuncAttributeMaxDynamicSharedMemorySize, SMEM_MMA);
    qkv_mma<<<dim3(KD / 128, MTOT / 128, 3), 256, SMEM_MMA>>>();

    cudaFuncSetAttribute(attn_mma, cudaFuncAttributeMaxDynamicSharedMemorySize, ATT_SMEM);
    attn_mma<<<dim3(TT / 64, NH, BB), 128, ATT_SMEM>>>();

    cudaFuncSetAttribute(out_mma, cudaFuncAttributeMaxDynamicSharedMemorySize, SMEM_MMA);
    out_mma<<<dim3(KD / 128, MTOT / 128), 256, SMEM_MMA>>>(bu, out);
}